// round 2
// baseline (speedup 1.0000x reference)
#include <cuda_runtime.h>
#include <math.h>

// Problem constants
#define BROWS 4096
#define EDIM  512
#define DDIM  768
#define NT    32          // 4096 / 128 j-tiles

// Scratch (static device globals: allocation-free)
__device__ float g_img[BROWS * EDIM];
__device__ float g_txt[BROWS * EDIM];
__device__ float g_sy[BROWS];
__device__ float g_partS[NT * BROWS];
__device__ float g_partD[NT * BROWS];
__device__ float g_row[2 * BROWS];

#define BM 128
#define BN 128
#define BK 32
#define LDS 132   // padded smem row stride (floats)

// ---------------------------------------------------------------------------
// Embed GEMM: C(which) = A[M,K] @ W[K,N], all row-major. M=4096,K=768,N=512
// ---------------------------------------------------------------------------
__global__ __launch_bounds__(256) void embed_gemm(const float* __restrict__ A,
                                                  const float* __restrict__ W,
                                                  int which, int M, int N, int K)
{
    __shared__ float As[BK][LDS];
    __shared__ float Bs[BK][LDS];
    float* C = which ? g_txt : g_img;
    const int tid = threadIdx.x;
    const int tx = tid & 15, ty = tid >> 4;
    const int m0 = blockIdx.y * BM, n0 = blockIdx.x * BN;

    float c[8][8] = {};

    for (int k0 = 0; k0 < K; k0 += BK) {
        // A tile, transposed into As[k][m]
        #pragma unroll
        for (int r = 0; r < 4; r++) {
            int idx = r * 1024 + tid * 4;
            int m = idx >> 5, k = idx & 31;
            float4 v = *(const float4*)(A + (size_t)(m0 + m) * K + k0 + k);
            As[k + 0][m] = v.x; As[k + 1][m] = v.y;
            As[k + 2][m] = v.z; As[k + 3][m] = v.w;
        }
        // W tile, direct into Bs[k][n]
        #pragma unroll
        for (int r = 0; r < 4; r++) {
            int idx = r * 1024 + tid * 4;
            int k = idx >> 7, n = idx & 127;
            *(float4*)&Bs[k][n] = *(const float4*)(W + (size_t)(k0 + k) * N + n0 + n);
        }
        __syncthreads();

        #pragma unroll
        for (int k = 0; k < BK; k++) {
            float a[8], b[8];
            *(float4*)&a[0] = *(const float4*)&As[k][ty * 8];
            *(float4*)&a[4] = *(const float4*)&As[k][ty * 8 + 4];
            *(float4*)&b[0] = *(const float4*)&Bs[k][tx * 8];
            *(float4*)&b[4] = *(const float4*)&Bs[k][tx * 8 + 4];
            #pragma unroll
            for (int i = 0; i < 8; i++)
                #pragma unroll
                for (int j = 0; j < 8; j++)
                    c[i][j] += a[i] * b[j];
        }
        __syncthreads();
    }

    #pragma unroll
    for (int i = 0; i < 8; i++)
        #pragma unroll
        for (int j = 0; j < 8; j += 4)
            *(float4*)(C + (size_t)(m0 + ty * 8 + i) * N + n0 + tx * 8 + j) =
                make_float4(c[i][j], c[i][j + 1], c[i][j + 2], c[i][j + 3]);
}

// ---------------------------------------------------------------------------
// Row L2 normalize (512 floats per row, 128 threads per row)
// ---------------------------------------------------------------------------
__global__ void normalize_k(int which)
{
    float* X = which ? g_txt : g_img;
    const int row = blockIdx.x;
    const int tid = threadIdx.x;   // 128
    float4* p = (float4*)(X + (size_t)row * EDIM);
    float4 v = p[tid];
    float s = v.x * v.x + v.y * v.y + v.z * v.z + v.w * v.w;
    #pragma unroll
    for (int o = 16; o > 0; o >>= 1) s += __shfl_xor_sync(0xffffffffu, s, o);
    __shared__ float red[4];
    if ((tid & 31) == 0) red[tid >> 5] = s;
    __syncthreads();
    float tot = red[0] + red[1] + red[2] + red[3];
    float r = 1.0f / sqrtf(tot);
    v.x *= r; v.y *= r; v.z *= r; v.w *= r;
    p[tid] = v;
}

// ---------------------------------------------------------------------------
// s_y[i] = dot(img_i, txt_{labels[i]})  (unscaled cosine)
// ---------------------------------------------------------------------------
__global__ void sy_k(const int* __restrict__ labels)
{
    const int row = blockIdx.x;
    const int tid = threadIdx.x;   // 128
    const int y = labels[row];
    float4 a = ((const float4*)(g_img + (size_t)row * EDIM))[tid];
    float4 b = ((const float4*)(g_txt + (size_t)y * EDIM))[tid];
    float s = a.x * b.x + a.y * b.y + a.z * b.z + a.w * b.w;
    #pragma unroll
    for (int o = 16; o > 0; o >>= 1) s += __shfl_xor_sync(0xffffffffu, s, o);
    __shared__ float red[4];
    if ((tid & 31) == 0) red[tid >> 5] = s;
    __syncthreads();
    if (tid == 0) g_sy[row] = red[0] + red[1] + red[2] + red[3];
}

// ---------------------------------------------------------------------------
// Fused logits GEMM (img @ txt^T) + softmax-partials epilogue.
// Fixed max M = scale (valid since |cos| <= 1): e = exp(scale*(c-1)).
// Per (jtile,row): partial S (all j) and partial D (masked j).
// ---------------------------------------------------------------------------
__global__ __launch_bounds__(256) void logits_k(const int* __restrict__ labels,
                                                const float* __restrict__ lsp)
{
    __shared__ float As[BK][LDS];
    __shared__ float Bs[BK][LDS];
    const int tid = threadIdx.x;
    const int tx = tid & 15, ty = tid >> 4;
    const int m0 = blockIdx.y * BM, n0 = blockIdx.x * BN;

    float c[8][8] = {};

    for (int k0 = 0; k0 < EDIM; k0 += BK) {
        #pragma unroll
        for (int r = 0; r < 4; r++) {
            int idx = r * 1024 + tid * 4;
            int m = idx >> 5, k = idx & 31;
            float4 v = *(const float4*)(g_img + (size_t)(m0 + m) * EDIM + k0 + k);
            As[k + 0][m] = v.x; As[k + 1][m] = v.y;
            As[k + 2][m] = v.z; As[k + 3][m] = v.w;
            float4 w = *(const float4*)(g_txt + (size_t)(n0 + m) * EDIM + k0 + k);
            Bs[k + 0][m] = w.x; Bs[k + 1][m] = w.y;
            Bs[k + 2][m] = w.z; Bs[k + 3][m] = w.w;
        }
        __syncthreads();

        #pragma unroll
        for (int k = 0; k < BK; k++) {
            float a[8], b[8];
            *(float4*)&a[0] = *(const float4*)&As[k][ty * 8];
            *(float4*)&a[4] = *(const float4*)&As[k][ty * 8 + 4];
            *(float4*)&b[0] = *(const float4*)&Bs[k][tx * 8];
            *(float4*)&b[4] = *(const float4*)&Bs[k][tx * 8 + 4];
            #pragma unroll
            for (int i = 0; i < 8; i++)
                #pragma unroll
                for (int j = 0; j < 8; j++)
                    c[i][j] += a[i] * b[j];
        }
        __syncthreads();
    }

    // ---- epilogue: exp + masked row-sum partials ----
    const float scale = expf(__ldg(lsp));
    const int rowB = m0 + ty * 8;
    const int colB = n0 + tx * 8;
    int labR[8], labC[8];
    float syv[8];
    #pragma unroll
    for (int i = 0; i < 8; i++) {
        labR[i] = labels[rowB + i];
        syv[i]  = g_sy[rowB + i];
        labC[i] = labels[colB + i];
    }
    float S[8] = {}, D[8] = {};
    #pragma unroll
    for (int i = 0; i < 8; i++) {
        #pragma unroll
        for (int j = 0; j < 8; j++) {
            float e = __expf(scale * (c[i][j] - 1.0f));
            S[i] += e;
            // mask: different label, not the y_i column itself, logit strictly greater
            if (labC[j] != labR[i] && (colB + j) != labR[i] && c[i][j] > syv[i])
                D[i] += e;
        }
    }

    // cross-tx reduction in (reused) smem: red[row_local][tx]
    float* redS = &As[0][0];   // needs 128*16 = 2048 floats (< 32*132)
    float* redD = &Bs[0][0];
    #pragma unroll
    for (int i = 0; i < 8; i++) {
        redS[(ty * 8 + i) * 16 + tx] = S[i];
        redD[(ty * 8 + i) * 16 + tx] = D[i];
    }
    __syncthreads();
    if (tid < 128) {
        float s = 0.f, d = 0.f;
        #pragma unroll
        for (int t = 0; t < 16; t++) {
            s += redS[tid * 16 + t];
            d += redD[tid * 16 + t];
        }
        g_partS[(size_t)blockIdx.x * BROWS + m0 + tid] = s;
        g_partD[(size_t)blockIdx.x * BROWS + m0 + tid] = d;
    }
}

// ---------------------------------------------------------------------------
// Per-row loss terms (deterministic fixed-order sum over 32 jtile partials)
// ---------------------------------------------------------------------------
__global__ void rowloss_k(const float* __restrict__ lsp)
{
    const int row = blockIdx.x * blockDim.x + threadIdx.x;
    const float scale = expf(*lsp);
    float S = 0.f, D = 0.f;
    #pragma unroll
    for (int t = 0; t < NT; t++) {
        S += g_partS[t * BROWS + row];
        D += g_partD[t * BROWS + row];
    }
    const float sy = g_sy[row] * scale;
    const float logp = (sy - scale) - logf(S);   // logp[i, y_i]
    const float p = expf(logp);
    const float denom = D / S;
    const float cmp = (D > 0.0f) ? p / (denom + 1e-10f) : 0.0f;
    g_row[row] = -logp;
    g_row[BROWS + row] = cmp;
}

// ---------------------------------------------------------------------------
// Final scalar: (sum clip_i + sum cmp_i) / B
// ---------------------------------------------------------------------------
__global__ void final_k(float* __restrict__ out)
{
    const int tid = threadIdx.x;  // 256
    float s = 0.f;
    for (int i = tid; i < 2 * BROWS; i += 256) s += g_row[i];
    #pragma unroll
    for (int o = 16; o > 0; o >>= 1) s += __shfl_xor_sync(0xffffffffu, s, o);
    __shared__ float red[8];
    if ((tid & 31) == 0) red[tid >> 5] = s;
    __syncthreads();
    if (tid == 0) {
        float t = 0.f;
        #pragma unroll
        for (int i = 0; i < 8; i++) t += red[i];
        out[0] = t / (float)BROWS;
    }
}

// ---------------------------------------------------------------------------
extern "C" void kernel_launch(void* const* d_in, const int* in_sizes, int n_in,
                              void* d_out, int out_size)
{
    const float* images = (const float*)d_in[0];
    const float* texts  = (const float*)d_in[1];
    const int*   labels = (const int*)d_in[2];
    const float* W_img  = (const float*)d_in[3];
    const float* W_txt  = (const float*)d_in[4];
    const float* lscale = (const float*)d_in[5];
    float* out = (float*)d_out;

    dim3 gE(EDIM / BN, BROWS / BM);     // (4, 32)
    embed_gemm<<<gE, 256>>>(images, W_img, 0, BROWS, EDIM, DDIM);
    embed_gemm<<<gE, 256>>>(texts,  W_txt, 1, BROWS, EDIM, DDIM);
    normalize_k<<<BROWS, 128>>>(0);
    normalize_k<<<BROWS, 128>>>(1);
    sy_k<<<BROWS, 128>>>(labels);
    dim3 gL(NT, NT);                    // (32, 32)
    logits_k<<<gL, 256>>>(labels, lscale);
    rowloss_k<<<32, 128>>>(lscale);
    final_k<<<1, 256>>>(out);
}

// round 4
// speedup vs baseline: 5.1314x; 5.1314x over previous
#include <cuda_runtime.h>
#include <cuda_bf16.h>
#include <math.h>
#include <stdint.h>

// Problem constants
#define BROWS 4096
#define EDIM  512
#define DDIM  768
#define NT    32          // 4096 / 128 j-tiles

// ---------------- device scratch (allocation-free) ----------------
__device__ __nv_bfloat16 g_ah [BROWS * DDIM];   // images bf16
__device__ __nv_bfloat16 g_bh [BROWS * DDIM];   // texts  bf16
__device__ __nv_bfloat16 g_wti[EDIM * DDIM];    // W_img^T bf16 [512,768] K-contig
__device__ __nv_bfloat16 g_wtt[EDIM * DDIM];    // W_txt^T bf16
__device__ float g_img[BROWS * EDIM];           // embed outputs fp32
__device__ float g_txt[BROWS * EDIM];
__device__ __nv_bfloat16 g_imgh[BROWS * EDIM];  // normalized bf16
__device__ __nv_bfloat16 g_txth[BROWS * EDIM];
__device__ float g_sy[BROWS];
__device__ float g_partS[NT * BROWS];
__device__ float g_partD[NT * BROWS];
__device__ float g_row[2 * BROWS];

// Smem map (dynamic): A buf0 @0, A buf1 @16384, B buf0 @32768, B buf1 @49152,
// labels @65536 (512B), partS @66048 (2KB), partD @68096 (2KB)
#define SMEM_TOTAL 70144

// ---------------- PTX helpers (all plain sm_80-era PTX) ----------------
__device__ __forceinline__ uint32_t s2u(const void* p) {
    uint32_t a;
    asm("{ .reg .u64 t; cvta.to.shared.u64 t, %1; cvt.u32.u64 %0, t; }"
        : "=r"(a) : "l"(p));
    return a;
}
__device__ __forceinline__ void cp16(uint32_t s, const void* g) {
    asm volatile("cp.async.cg.shared.global [%0], [%1], 16;" :: "r"(s), "l"(g));
}
__device__ __forceinline__ void cp_commit() { asm volatile("cp.async.commit_group;"); }
__device__ __forceinline__ void cp_wait0()  { asm volatile("cp.async.wait_group 0;"); }
__device__ __forceinline__ void cp_wait1()  { asm volatile("cp.async.wait_group 1;"); }

__device__ __forceinline__ void ldsm4(uint32_t* r, uint32_t addr) {
    asm volatile("ldmatrix.sync.aligned.m8n8.x4.shared.b16 {%0,%1,%2,%3}, [%4];"
                 : "=r"(r[0]), "=r"(r[1]), "=r"(r[2]), "=r"(r[3]) : "r"(addr));
}
__device__ __forceinline__ void mma16816(float* c, const uint32_t* a,
                                         uint32_t b0, uint32_t b1) {
    asm volatile(
        "mma.sync.aligned.m16n8k16.row.col.f32.bf16.bf16.f32 "
        "{%0,%1,%2,%3}, {%4,%5,%6,%7}, {%8,%9}, {%0,%1,%2,%3};"
        : "+f"(c[0]), "+f"(c[1]), "+f"(c[2]), "+f"(c[3])
        : "r"(a[0]), "r"(a[1]), "r"(a[2]), "r"(a[3]), "r"(b0), "r"(b1));
}

// Load one 128x64 bf16 tile pair (A and B) into buf with SW128 swizzle.
template<int KEL>
__device__ __forceinline__ void load_tiles(uint32_t sb, int buf,
    const __nv_bfloat16* __restrict__ A, const __nv_bfloat16* __restrict__ B,
    int k0)
{
    const int tid = threadIdx.x;
    #pragma unroll
    for (int i = 0; i < 4; i++) {
        int idx = i * 256 + tid;
        int row = idx >> 3, ch = idx & 7;
        uint32_t soff = (uint32_t)buf * 16384u + (uint32_t)row * 128u +
                        ((uint32_t)(ch ^ (row & 7)) << 4);
        const __nv_bfloat16* ga = A + (size_t)row * KEL + k0 + ch * 8;
        const __nv_bfloat16* gb = B + (size_t)row * KEL + k0 + ch * 8;
        cp16(sb + soff, ga);
        cp16(sb + 32768u + soff, gb);
    }
}

// MMA over one 128x128x64 buffer; accum c[mt][nt][4]
__device__ __forceinline__ void compute_buf(uint32_t sb, int buf,
    int warp_m, int warp_n, int lane, float c[4][4][4])
{
    const int l15 = lane & 15, lhi = lane >> 4;
    const uint32_t abase = sb + (uint32_t)buf * 16384u;
    const uint32_t bbase = sb + 32768u + (uint32_t)buf * 16384u;
    const int arow = warp_m * 64 + l15;
    const int brow = warp_n * 32 + l15;
    #pragma unroll
    for (int kk = 0; kk < 4; kk++) {
        const int ch = kk * 2 + lhi;
        uint32_t a[4][4];
        #pragma unroll
        for (int mt = 0; mt < 4; mt++) {
            int r = arow + mt * 16;
            ldsm4(a[mt], abase + (uint32_t)r * 128u + ((uint32_t)(ch ^ (r & 7)) << 4));
        }
        uint32_t b[2][4];
        #pragma unroll
        for (int h = 0; h < 2; h++) {
            int r = brow + h * 16;
            ldsm4(b[h], bbase + (uint32_t)r * 128u + ((uint32_t)(ch ^ (r & 7)) << 4));
        }
        #pragma unroll
        for (int mt = 0; mt < 4; mt++)
            #pragma unroll
            for (int nt = 0; nt < 4; nt++)
                mma16816(c[mt][nt], a[mt], b[nt >> 1][nt & 1], b[nt >> 1][2 + (nt & 1)]);
    }
}

// Full 128x128 GEMM mainloop, K = KEL (multiple of 64), double-buffered cp.async
template<int KEL>
__device__ __forceinline__ void mma_gemm(uint32_t sb,
    const __nv_bfloat16* __restrict__ A, const __nv_bfloat16* __restrict__ B,
    float c[4][4][4])
{
    constexpr int NS = KEL / 64;
    const int tid = threadIdx.x, lane = tid & 31, warp = tid >> 5;
    const int warp_m = warp >> 2, warp_n = warp & 3;

    load_tiles<KEL>(sb, 0, A, B, 0);
    cp_commit();
    for (int s = 0; s < NS; s++) {
        if (s + 1 < NS) {
            load_tiles<KEL>(sb, (s + 1) & 1, A, B, (s + 1) * 64);
            cp_commit();
            cp_wait1();
        } else {
            cp_wait0();
        }
        __syncthreads();
        compute_buf(sb, s & 1, warp_m, warp_n, lane, c);
        __syncthreads();
    }
}

// ---------------------------------------------------------------------------
// fp32 -> bf16 conversion (images / texts)
// ---------------------------------------------------------------------------
__global__ void cvt_k(const float* __restrict__ src, int which, int n4)
{
    __nv_bfloat16* dst = which ? g_bh : g_ah;
    int i = blockIdx.x * blockDim.x + threadIdx.x;
    const int stride = gridDim.x * blockDim.x;
    for (; i < n4; i += stride) {
        float4 v = ((const float4*)src)[i];
        ((__nv_bfloat162*)dst)[2 * i]     = __floats2bfloat162_rn(v.x, v.y);
        ((__nv_bfloat162*)dst)[2 * i + 1] = __floats2bfloat162_rn(v.z, v.w);
    }
}

// W [K=768, N=512] fp32 -> W^T [512, 768] bf16
__global__ void transpose_k(const float* __restrict__ W, int which)
{
    __nv_bfloat16* Wt = which ? g_wtt : g_wti;
    __shared__ float t[32][33];
    const int n0 = blockIdx.x * 32, k0 = blockIdx.y * 32;
    const int tx = threadIdx.x, ty = threadIdx.y;
    t[ty][tx] = W[(size_t)(k0 + ty) * EDIM + n0 + tx];
    __syncthreads();
    Wt[(size_t)(n0 + ty) * DDIM + k0 + tx] = __float2bfloat16_rn(t[tx][ty]);
}

// ---------------------------------------------------------------------------
// Embed GEMM: C fp32 [4096,512] = A_bf16 [4096,768] @ Wt_bf16 [512,768]^T
// ---------------------------------------------------------------------------
__global__ __launch_bounds__(256, 1) void embed_mma(int which)
{
    extern __shared__ char smem[];
    const uint32_t sb = s2u(smem);
    const __nv_bfloat16* A  = which ? g_bh  : g_ah;
    const __nv_bfloat16* Wt = which ? g_wtt : g_wti;
    float* C = which ? g_txt : g_img;
    const int m0 = blockIdx.y * 128, n0 = blockIdx.x * 128;

    float c[4][4][4] = {};
    mma_gemm<DDIM>(sb, A + (size_t)m0 * DDIM, Wt + (size_t)n0 * DDIM, c);

    const int lane = threadIdx.x & 31, warp = threadIdx.x >> 5;
    const int g = lane >> 2, tig = lane & 3;
    const int warp_m = warp >> 2, warp_n = warp & 3;
    #pragma unroll
    for (int mt = 0; mt < 4; mt++) {
        const int row = m0 + warp_m * 64 + mt * 16 + g;
        #pragma unroll
        for (int nt = 0; nt < 4; nt++) {
            const int col = n0 + warp_n * 32 + nt * 8 + tig * 2;
            *(float2*)(C + (size_t)row * EDIM + col) =
                make_float2(c[mt][nt][0], c[mt][nt][1]);
            *(float2*)(C + (size_t)(row + 8) * EDIM + col) =
                make_float2(c[mt][nt][2], c[mt][nt][3]);
        }
    }
}

// ---------------------------------------------------------------------------
// Row L2 normalize: fp32 embed -> bf16 normalized
// ---------------------------------------------------------------------------
__global__ void normalize_k(int which)
{
    const float* X = which ? g_txt : g_img;
    __nv_bfloat16* Xh = which ? g_txth : g_imgh;
    const int row = blockIdx.x;
    const int tid = threadIdx.x;   // 128
    float4 v = ((const float4*)(X + (size_t)row * EDIM))[tid];
    float s = v.x * v.x + v.y * v.y + v.z * v.z + v.w * v.w;
    #pragma unroll
    for (int o = 16; o > 0; o >>= 1) s += __shfl_xor_sync(0xffffffffu, s, o);
    __shared__ float red[4];
    if ((tid & 31) == 0) red[tid >> 5] = s;
    __syncthreads();
    const float r = 1.0f / sqrtf(red[0] + red[1] + red[2] + red[3]);
    ((__nv_bfloat162*)(Xh + (size_t)row * EDIM))[2 * tid] =
        __floats2bfloat162_rn(v.x * r, v.y * r);
    ((__nv_bfloat162*)(Xh + (size_t)row * EDIM))[2 * tid + 1] =
        __floats2bfloat162_rn(v.z * r, v.w * r);
}

// ---------------------------------------------------------------------------
// s_y[i] = dot(imgh_i, txth_{labels[i]}) in fp32 (same bf16 vectors as GEMM)
// ---------------------------------------------------------------------------
__global__ void sy_k(const int* __restrict__ labels)
{
    const int row = blockIdx.x;
    const int tid = threadIdx.x;   // 128
    const int y = labels[row];
    const __nv_bfloat162* a = (const __nv_bfloat162*)(g_imgh + (size_t)row * EDIM);
    const __nv_bfloat162* b = (const __nv_bfloat162*)(g_txth + (size_t)y * EDIM);
    float s = 0.f;
    #pragma unroll
    for (int r = 0; r < 2; r++) {
        float2 af = __bfloat1622float2(a[tid * 2 + r]);
        float2 bf = __bfloat1622float2(b[tid * 2 + r]);
        s += af.x * bf.x + af.y * bf.y;
    }
    #pragma unroll
    for (int o = 16; o > 0; o >>= 1) s += __shfl_xor_sync(0xffffffffu, s, o);
    __shared__ float red[4];
    if ((tid & 31) == 0) red[tid >> 5] = s;
    __syncthreads();
    if (tid == 0) g_sy[row] = red[0] + red[1] + red[2] + red[3];
}

// ---------------------------------------------------------------------------
// Logits GEMM (imgh @ txth^T) + fused softmax-partials epilogue.
// Fixed max M = scale (|cos| <= 1): e = exp(scale*(c-1)).
// ---------------------------------------------------------------------------
__global__ __launch_bounds__(256, 1) void logits_mma(const int* __restrict__ labels,
                                                     const float* __restrict__ lsp)
{
    extern __shared__ char smem[];
    const uint32_t sb = s2u(smem);
    int*   slab = (int*)(smem + 65536);
    float* pS   = (float*)(smem + 66048);
    float* pD   = (float*)(smem + 68096);
    const int m0 = blockIdx.y * 128, n0 = blockIdx.x * 128;
    const int tid = threadIdx.x;
    if (tid < 128) slab[tid] = labels[n0 + tid];

    float c[4][4][4] = {};
    mma_gemm<EDIM>(sb, g_imgh + (size_t)m0 * EDIM, g_txth + (size_t)n0 * EDIM, c);

    const int lane = tid & 31, warp = tid >> 5;
    const int g = lane >> 2, tig = lane & 3;
    const int warp_m = warp >> 2, warp_n = warp & 3;
    const float scale = expf(__ldg(lsp));

    #pragma unroll
    for (int mt = 0; mt < 4; mt++) {
        const int rl = warp_m * 64 + mt * 16 + g;       // local row (lo)
        const int rlo = m0 + rl, rhi = rlo + 8;
        const int lab_lo = __ldg(labels + rlo), lab_hi = __ldg(labels + rhi);
        const float sy_lo = __ldg(g_sy + rlo), sy_hi = __ldg(g_sy + rhi);
        float Slo = 0.f, Dlo = 0.f, Shi = 0.f, Dhi = 0.f;
        #pragma unroll
        for (int nt = 0; nt < 4; nt++) {
            const int jl = warp_n * 32 + nt * 8 + tig * 2;
            const int lab0 = slab[jl], lab1 = slab[jl + 1];
            const int j0 = n0 + jl, j1 = j0 + 1;
            float v, e;
            v = c[mt][nt][0]; e = __expf(scale * (v - 1.0f)); Slo += e;
            if (lab0 != lab_lo && j0 != lab_lo && v > sy_lo) Dlo += e;
            v = c[mt][nt][1]; e = __expf(scale * (v - 1.0f)); Slo += e;
            if (lab1 != lab_lo && j1 != lab_lo && v > sy_lo) Dlo += e;
            v = c[mt][nt][2]; e = __expf(scale * (v - 1.0f)); Shi += e;
            if (lab0 != lab_hi && j0 != lab_hi && v > sy_hi) Dhi += e;
            v = c[mt][nt][3]; e = __expf(scale * (v - 1.0f)); Shi += e;
            if (lab1 != lab_hi && j1 != lab_hi && v > sy_hi) Dhi += e;
        }
        // reduce across the 4 quad lanes (tig)
        #pragma unroll
        for (int o = 1; o < 4; o <<= 1) {
            Slo += __shfl_xor_sync(0xffffffffu, Slo, o);
            Dlo += __shfl_xor_sync(0xffffffffu, Dlo, o);
            Shi += __shfl_xor_sync(0xffffffffu, Shi, o);
            Dhi += __shfl_xor_sync(0xffffffffu, Dhi, o);
        }
        if (tig == 0) {
            pS[rl * 4 + warp_n] = Slo;  pD[rl * 4 + warp_n] = Dlo;
            pS[(rl + 8) * 4 + warp_n] = Shi;  pD[(rl + 8) * 4 + warp_n] = Dhi;
        }
    }
    __syncthreads();
    if (tid < 128) {
        float S = pS[tid * 4] + pS[tid * 4 + 1] + pS[tid * 4 + 2] + pS[tid * 4 + 3];
        float D = pD[tid * 4] + pD[tid * 4 + 1] + pD[tid * 4 + 2] + pD[tid * 4 + 3];
        g_partS[(size_t)blockIdx.x * BROWS + m0 + tid] = S;
        g_partD[(size_t)blockIdx.x * BROWS + m0 + tid] = D;
    }
}

// ---------------------------------------------------------------------------
// Per-row loss terms (deterministic fixed-order sum over 32 jtile partials)
// ---------------------------------------------------------------------------
__global__ void rowloss_k(const float* __restrict__ lsp)
{
    const int row = blockIdx.x * blockDim.x + threadIdx.x;
    const float scale = expf(*lsp);
    float S = 0.f, D = 0.f;
    #pragma unroll
    for (int t = 0; t < NT; t++) {
        S += g_partS[t * BROWS + row];
        D += g_partD[t * BROWS + row];
    }
    const float sy = g_sy[row] * scale;
    const float logp = (sy - scale) - logf(S);
    const float p = expf(logp);
    const float denom = D / S;
    const float cmp = (D > 0.0f) ? p / (denom + 1e-10f) : 0.0f;
    g_row[row] = -logp;
    g_row[BROWS + row] = cmp;
}

__global__ void final_k(float* __restrict__ out)
{
    const int tid = threadIdx.x;  // 256
    float s = 0.f;
    for (int i = tid; i < 2 * BROWS; i += 256) s += g_row[i];
    #pragma unroll
    for (int o = 16; o > 0; o >>= 1) s += __shfl_xor_sync(0xffffffffu, s, o);
    __shared__ float red[8];
    if ((tid & 31) == 0) red[tid >> 5] = s;
    __syncthreads();
    if (tid == 0) {
        float t = 0.f;
        #pragma unroll
        for (int i = 0; i < 8; i++) t += red[i];
        out[0] = t / (float)BROWS;
    }
}

// ---------------------------------------------------------------------------
extern "C" void kernel_launch(void* const* d_in, const int* in_sizes, int n_in,
                              void* d_out, int out_size)
{
    const float* images = (const float*)d_in[0];
    const float* texts  = (const float*)d_in[1];
    const int*   labels = (const int*)d_in[2];
    const float* W_img  = (const float*)d_in[3];
    const float* W_txt  = (const float*)d_in[4];
    const float* lscale = (const float*)d_in[5];
    float* out = (float*)d_out;

    // Idempotent, deterministic; needed for >48KB dynamic smem.
    cudaFuncSetAttribute(embed_mma,  cudaFuncAttributeMaxDynamicSharedMemorySize, SMEM_TOTAL);
    cudaFuncSetAttribute(logits_mma, cudaFuncAttributeMaxDynamicSharedMemorySize, SMEM_TOTAL);

    const int n4 = BROWS * DDIM / 4;
    cvt_k<<<1024, 256>>>(images, 0, n4);
    cvt_k<<<1024, 256>>>(texts,  1, n4);
    dim3 gT(EDIM / 32, DDIM / 32);
    transpose_k<<<gT, dim3(32, 32)>>>(W_img, 0);
    transpose_k<<<gT, dim3(32, 32)>>>(W_txt, 1);

    dim3 gE(EDIM / 128, BROWS / 128);          // (4, 32)
    embed_mma<<<gE, 256, SMEM_TOTAL>>>(0);
    embed_mma<<<gE, 256, SMEM_TOTAL>>>(1);

    normalize_k<<<BROWS, 128>>>(0);
    normalize_k<<<BROWS, 128>>>(1);
    sy_k<<<BROWS, 128>>>(labels);

    dim3 gL(NT, NT);                           // (32, 32)
    logits_mma<<<gL, 256, SMEM_TOTAL>>>(labels, lscale);

    rowloss_k<<<32, 128>>>(lscale);
    final_k<<<1, 256>>>(out);
}

// round 5
// speedup vs baseline: 5.5271x; 1.0771x over previous
#include <cuda_runtime.h>
#include <cuda_bf16.h>
#include <math.h>
#include <stdint.h>

// Problem constants
#define BROWS 4096
#define EDIM  512
#define DDIM  768
#define NT    32          // 4096 / 128 j-tiles

// ---------------- device scratch (allocation-free) ----------------
__device__ __nv_bfloat16 g_ah [BROWS * DDIM];   // images bf16
__device__ __nv_bfloat16 g_bh [BROWS * DDIM];   // texts  bf16
__device__ __nv_bfloat16 g_wti[EDIM * DDIM];    // W_img^T bf16 [512,768] K-contig
__device__ __nv_bfloat16 g_wtt[EDIM * DDIM];    // W_txt^T bf16
__device__ __nv_bfloat16 g_imgh[BROWS * EDIM];  // normalized bf16
__device__ __nv_bfloat16 g_txth[BROWS * EDIM];
__device__ float g_sy[BROWS];
__device__ float g_partS[NT * BROWS];
__device__ float g_partD[NT * BROWS];
__device__ float g_row[2 * BROWS];

// ---------------- PTX helpers (plain sm_80-era PTX) ----------------
__device__ __forceinline__ uint32_t s2u(const void* p) {
    uint32_t a;
    asm("{ .reg .u64 t; cvta.to.shared.u64 t, %1; cvt.u32.u64 %0, t; }"
        : "=r"(a) : "l"(p));
    return a;
}
__device__ __forceinline__ void cp16(uint32_t s, const void* g) {
    asm volatile("cp.async.cg.shared.global [%0], [%1], 16;" :: "r"(s), "l"(g));
}
__device__ __forceinline__ void cp_commit() { asm volatile("cp.async.commit_group;"); }
__device__ __forceinline__ void cp_wait0()  { asm volatile("cp.async.wait_group 0;"); }
__device__ __forceinline__ void cp_wait1()  { asm volatile("cp.async.wait_group 1;"); }

__device__ __forceinline__ void ldsm4(uint32_t* r, uint32_t addr) {
    asm volatile("ldmatrix.sync.aligned.m8n8.x4.shared.b16 {%0,%1,%2,%3}, [%4];"
                 : "=r"(r[0]), "=r"(r[1]), "=r"(r[2]), "=r"(r[3]) : "r"(addr));
}
__device__ __forceinline__ void mma16816(float* c, const uint32_t* a,
                                         uint32_t b0, uint32_t b1) {
    asm volatile(
        "mma.sync.aligned.m16n8k16.row.col.f32.bf16.bf16.f32 "
        "{%0,%1,%2,%3}, {%4,%5,%6,%7}, {%8,%9}, {%0,%1,%2,%3};"
        : "+f"(c[0]), "+f"(c[1]), "+f"(c[2]), "+f"(c[3])
        : "r"(a[0]), "r"(a[1]), "r"(a[2]), "r"(a[3]), "r"(b0), "r"(b1));
}

// Load ROWS x 64 bf16 (128B rows, SW128 xor swizzle) via cp.async; 256 threads.
template<int ROWS, int KEL>
__device__ __forceinline__ void load_rows(uint32_t sdst,
    const __nv_bfloat16* __restrict__ G, int k0)
{
    const int tid = threadIdx.x;
    #pragma unroll
    for (int i = 0; i < ROWS * 8 / 256; i++) {
        int idx = i * 256 + tid;
        int row = idx >> 3, ch = idx & 7;
        uint32_t soff = (uint32_t)row * 128u + ((uint32_t)(ch ^ (row & 7)) << 4);
        cp16(sdst + soff, G + (size_t)row * KEL + k0 + ch * 8);
    }
}

// ---------------------------------------------------------------------------
// fp32 -> bf16 conversion, both inputs in one launch (y = which)
// ---------------------------------------------------------------------------
__global__ void cvt2_k(const float* __restrict__ img, const float* __restrict__ txt)
{
    const int which = blockIdx.y;
    const float* src = which ? txt : img;
    __nv_bfloat16* dst = which ? g_bh : g_ah;
    int i = blockIdx.x * blockDim.x + threadIdx.x;    // grid.x*256 == n4
    float4 v = ((const float4*)src)[i];
    ((__nv_bfloat162*)dst)[2 * i]     = __floats2bfloat162_rn(v.x, v.y);
    ((__nv_bfloat162*)dst)[2 * i + 1] = __floats2bfloat162_rn(v.z, v.w);
}

// W [K=768, N=512] fp32 -> W^T [512, 768] bf16, both weights in one launch (z)
__global__ void transpose2_k(const float* __restrict__ Wi, const float* __restrict__ Wt2)
{
    const int which = blockIdx.z;
    const float* W = which ? Wt2 : Wi;
    __nv_bfloat16* Wt = which ? g_wtt : g_wti;
    __shared__ float t[32][33];
    const int n0 = blockIdx.x * 32, k0 = blockIdx.y * 32;
    const int tx = threadIdx.x, ty = threadIdx.y;
    t[ty][tx] = W[(size_t)(k0 + ty) * EDIM + n0 + tx];
    __syncthreads();
    Wt[(size_t)(n0 + ty) * DDIM + k0 + tx] = __float2bfloat16_rn(t[tx][ty]);
}

// ---------------------------------------------------------------------------
// Fused embed GEMM + row L2-normalize.
// C[64,512] = A_bf16[64,768] @ Wt_bf16[512,768]^T, then row-normalize -> bf16.
// 8 warps, each owns all 64 rows x 64 cols. 3-stage cp.async pipeline.
// Smem: stage st at st*73728: A [0,8K), B [8K,72K).
// ---------------------------------------------------------------------------
#define EN_STAGE 73728
#define EN_SMEM  (3 * EN_STAGE)   // 221184

__global__ __launch_bounds__(256, 1) void embed_norm_k()
{
    extern __shared__ char smem[];
    const uint32_t sb = s2u(smem);
    const int which = blockIdx.y;
    const __nv_bfloat16* A  = (which ? g_bh  : g_ah) + (size_t)blockIdx.x * 64 * DDIM;
    const __nv_bfloat16* Wt = which ? g_wtt : g_wti;
    __nv_bfloat16* out = which ? g_txth : g_imgh;
    const int m0 = blockIdx.x * 64;

    const int tid = threadIdx.x, lane = tid & 31, w = tid >> 5;
    const int l15 = lane & 15, lhi = lane >> 4;
    const int g = lane >> 2, tig = lane & 3;

    float c[4][8][4] = {};

    constexpr int ITERS = DDIM / 64;   // 12
    // prologue: stages 0,1
    #pragma unroll
    for (int p = 0; p < 2; p++) {
        load_rows<64,  DDIM>(sb + p * EN_STAGE,        A,  p * 64);
        load_rows<512, DDIM>(sb + p * EN_STAGE + 8192, Wt, p * 64);
        cp_commit();
    }
    for (int s = 0; s < ITERS; s++) {
        if (s == ITERS - 1) cp_wait0(); else cp_wait1();
        __syncthreads();
        if (s + 2 < ITERS) {
            const int d = (s + 2) % 3;
            load_rows<64,  DDIM>(sb + d * EN_STAGE,        A,  (s + 2) * 64);
            load_rows<512, DDIM>(sb + d * EN_STAGE + 8192, Wt, (s + 2) * 64);
            cp_commit();
        }
        const uint32_t abase = sb + (s % 3) * EN_STAGE;
        const uint32_t bbase = abase + 8192;
        #pragma unroll
        for (int kk = 0; kk < 4; kk++) {
            const int ch = kk * 2 + lhi;
            uint32_t a[4][4];
            #pragma unroll
            for (int mt = 0; mt < 4; mt++) {
                int r = l15 + mt * 16;
                ldsm4(a[mt], abase + (uint32_t)r * 128u + ((uint32_t)(ch ^ (r & 7)) << 4));
            }
            uint32_t b[4][4];
            #pragma unroll
            for (int h = 0; h < 4; h++) {
                int r = w * 64 + h * 16 + l15;
                ldsm4(b[h], bbase + (uint32_t)r * 128u + ((uint32_t)(ch ^ (r & 7)) << 4));
            }
            #pragma unroll
            for (int mt = 0; mt < 4; mt++)
                #pragma unroll
                for (int nt = 0; nt < 8; nt++)
                    mma16816(c[mt][nt], a[mt], b[nt >> 1][nt & 1], b[nt >> 1][2 + (nt & 1)]);
        }
        __syncthreads();
    }

    // ---- epilogue: row norms (reuse stage-0 smem) ----
    float* nsm = (float*)smem;   // [64][8] partials, then rnorm at [512..575]
    #pragma unroll
    for (int mt = 0; mt < 4; mt++) {
        float plo = 0.f, phi = 0.f;
        #pragma unroll
        for (int nt = 0; nt < 8; nt++) {
            plo += c[mt][nt][0] * c[mt][nt][0] + c[mt][nt][1] * c[mt][nt][1];
            phi += c[mt][nt][2] * c[mt][nt][2] + c[mt][nt][3] * c[mt][nt][3];
        }
        #pragma unroll
        for (int o = 1; o < 4; o <<= 1) {
            plo += __shfl_xor_sync(0xffffffffu, plo, o);
            phi += __shfl_xor_sync(0xffffffffu, phi, o);
        }
        if (tig == 0) {
            nsm[(mt * 16 + g) * 8 + w] = plo;
            nsm[(mt * 16 + g + 8) * 8 + w] = phi;
        }
    }
    __syncthreads();
    if (tid < 64) {
        float s = 0.f;
        #pragma unroll
        for (int i = 0; i < 8; i++) s += nsm[tid * 8 + i];
        nsm[512 + tid] = 1.0f / sqrtf(s);
    }
    __syncthreads();
    #pragma unroll
    for (int mt = 0; mt < 4; mt++) {
        const int rl = mt * 16 + g;
        const float rlo = nsm[512 + rl], rhi = nsm[512 + rl + 8];
        #pragma unroll
        for (int nt = 0; nt < 8; nt++) {
            const int col = w * 64 + nt * 8 + tig * 2;
            *(__nv_bfloat162*)(out + (size_t)(m0 + rl) * EDIM + col) =
                __floats2bfloat162_rn(c[mt][nt][0] * rlo, c[mt][nt][1] * rlo);
            *(__nv_bfloat162*)(out + (size_t)(m0 + rl + 8) * EDIM + col) =
                __floats2bfloat162_rn(c[mt][nt][2] * rhi, c[mt][nt][3] * rhi);
        }
    }
}

// ---------------------------------------------------------------------------
// s_y[i] = dot(imgh_i, txth_{labels[i]}) in fp32 (same bf16 vectors as GEMM)
// ---------------------------------------------------------------------------
__global__ void sy_k(const int* __restrict__ labels)
{
    const int row = blockIdx.x;
    const int tid = threadIdx.x;   // 128
    const int y = labels[row];
    const __nv_bfloat162* a = (const __nv_bfloat162*)(g_imgh + (size_t)row * EDIM);
    const __nv_bfloat162* b = (const __nv_bfloat162*)(g_txth + (size_t)y * EDIM);
    float s = 0.f;
    #pragma unroll
    for (int r = 0; r < 2; r++) {
        float2 af = __bfloat1622float2(a[tid * 2 + r]);
        float2 bf = __bfloat1622float2(b[tid * 2 + r]);
        s += af.x * bf.x + af.y * bf.y;
    }
    #pragma unroll
    for (int o = 16; o > 0; o >>= 1) s += __shfl_xor_sync(0xffffffffu, s, o);
    __shared__ float red[4];
    if ((tid & 31) == 0) red[tid >> 5] = s;
    __syncthreads();
    if (tid == 0) g_sy[row] = red[0] + red[1] + red[2] + red[3];
}

// ---------------------------------------------------------------------------
// Logits GEMM (imgh @ txth^T) + fused softmax-partials epilogue.
// 128x128 tile, 3-stage cp.async pipeline, one barrier per stage.
// Smem: stage st at st*32768: A [0,16K), B [16K,32K); labels @98304,
// pS @98816, pD @100864. Total 102912.
// ---------------------------------------------------------------------------
#define LG_SMEM 102912

__global__ __launch_bounds__(256, 1) void logits_mma(const int* __restrict__ labels,
                                                     const float* __restrict__ lsp)
{
    extern __shared__ char smem[];
    const uint32_t sb = s2u(smem);
    int*   slab = (int*)(smem + 98304);
    float* pS   = (float*)(smem + 98816);
    float* pD   = (float*)(smem + 100864);
    const int m0 = blockIdx.y * 128, n0 = blockIdx.x * 128;
    const int tid = threadIdx.x;
    if (tid < 128) slab[tid] = labels[n0 + tid];

    const __nv_bfloat16* A = g_imgh + (size_t)m0 * EDIM;
    const __nv_bfloat16* B = g_txth + (size_t)n0 * EDIM;
    const int lane = tid & 31, warp = tid >> 5;
    const int l15 = lane & 15, lhi = lane >> 4;
    const int warp_m = warp >> 2, warp_n = warp & 3;

    float c[4][4][4] = {};

    constexpr int ITERS = EDIM / 64;   // 8
    #pragma unroll
    for (int p = 0; p < 2; p++) {
        load_rows<128, EDIM>(sb + p * 32768u,          A, p * 64);
        load_rows<128, EDIM>(sb + p * 32768u + 16384u, B, p * 64);
        cp_commit();
    }
    for (int s = 0; s < ITERS; s++) {
        if (s == ITERS - 1) cp_wait0(); else cp_wait1();
        __syncthreads();
        if (s + 2 < ITERS) {
            const int d = (s + 2) % 3;
            load_rows<128, EDIM>(sb + d * 32768u,          A, (s + 2) * 64);
            load_rows<128, EDIM>(sb + d * 32768u + 16384u, B, (s + 2) * 64);
            cp_commit();
        }
        const uint32_t abase = sb + (uint32_t)(s % 3) * 32768u;
        const uint32_t bbase = abase + 16384u;
        const int arow = warp_m * 64 + l15;
        const int brow = warp_n * 32 + l15;
        #pragma unroll
        for (int kk = 0; kk < 4; kk++) {
            const int ch = kk * 2 + lhi;
            uint32_t a[4][4];
            #pragma unroll
            for (int mt = 0; mt < 4; mt++) {
                int r = arow + mt * 16;
                ldsm4(a[mt], abase + (uint32_t)r * 128u + ((uint32_t)(ch ^ (r & 7)) << 4));
            }
            uint32_t b[2][4];
            #pragma unroll
            for (int h = 0; h < 2; h++) {
                int r = brow + h * 16;
                ldsm4(b[h], bbase + (uint32_t)r * 128u + ((uint32_t)(ch ^ (r & 7)) << 4));
            }
            #pragma unroll
            for (int mt = 0; mt < 4; mt++)
                #pragma unroll
                for (int nt = 0; nt < 4; nt++)
                    mma16816(c[mt][nt], a[mt], b[nt >> 1][nt & 1], b[nt >> 1][2 + (nt & 1)]);
        }
        __syncthreads();
    }

    // ---- epilogue: exp + masked row-sum partials ----
    const int g = lane >> 2, tig = lane & 3;
    const float scale = expf(__ldg(lsp));

    #pragma unroll
    for (int mt = 0; mt < 4; mt++) {
        const int rl = warp_m * 64 + mt * 16 + g;
        const int rlo = m0 + rl, rhi = rlo + 8;
        const int lab_lo = __ldg(labels + rlo), lab_hi = __ldg(labels + rhi);
        const float sy_lo = __ldg(g_sy + rlo), sy_hi = __ldg(g_sy + rhi);
        float Slo = 0.f, Dlo = 0.f, Shi = 0.f, Dhi = 0.f;
        #pragma unroll
        for (int nt = 0; nt < 4; nt++) {
            const int jl = warp_n * 32 + nt * 8 + tig * 2;
            const int lab0 = slab[jl], lab1 = slab[jl + 1];
            const int j0 = n0 + jl, j1 = j0 + 1;
            float v, e;
            v = c[mt][nt][0]; e = __expf(scale * (v - 1.0f)); Slo += e;
            if (lab0 != lab_lo && j0 != lab_lo && v > sy_lo) Dlo += e;
            v = c[mt][nt][1]; e = __expf(scale * (v - 1.0f)); Slo += e;
            if (lab1 != lab_lo && j1 != lab_lo && v > sy_lo) Dlo += e;
            v = c[mt][nt][2]; e = __expf(scale * (v - 1.0f)); Shi += e;
            if (lab0 != lab_hi && j0 != lab_hi && v > sy_hi) Dhi += e;
            v = c[mt][nt][3]; e = __expf(scale * (v - 1.0f)); Shi += e;
            if (lab1 != lab_hi && j1 != lab_hi && v > sy_hi) Dhi += e;
        }
        #pragma unroll
        for (int o = 1; o < 4; o <<= 1) {
            Slo += __shfl_xor_sync(0xffffffffu, Slo, o);
            Dlo += __shfl_xor_sync(0xffffffffu, Dlo, o);
            Shi += __shfl_xor_sync(0xffffffffu, Shi, o);
            Dhi += __shfl_xor_sync(0xffffffffu, Dhi, o);
        }
        if (tig == 0) {
            pS[rl * 4 + warp_n] = Slo;  pD[rl * 4 + warp_n] = Dlo;
            pS[(rl + 8) * 4 + warp_n] = Shi;  pD[(rl + 8) * 4 + warp_n] = Dhi;
        }
    }
    __syncthreads();
    if (tid < 128) {
        float S = pS[tid * 4] + pS[tid * 4 + 1] + pS[tid * 4 + 2] + pS[tid * 4 + 3];
        float D = pD[tid * 4] + pD[tid * 4 + 1] + pD[tid * 4 + 2] + pD[tid * 4 + 3];
        g_partS[(size_t)blockIdx.x * BROWS + m0 + tid] = S;
        g_partD[(size_t)blockIdx.x * BROWS + m0 + tid] = D;
    }
}

// ---------------------------------------------------------------------------
// Per-row loss terms (deterministic fixed-order sum over 32 jtile partials)
// ---------------------------------------------------------------------------
__global__ void rowloss_k(const float* __restrict__ lsp)
{
    const int row = blockIdx.x * blockDim.x + threadIdx.x;
    const float scale = expf(*lsp);
    float S = 0.f, D = 0.f;
    #pragma unroll
    for (int t = 0; t < NT; t++) {
        S += g_partS[t * BROWS + row];
        D += g_partD[t * BROWS + row];
    }
    const float sy = g_sy[row] * scale;
    const float logp = (sy - scale) - logf(S);
    const float p = expf(logp);
    const float denom = D / S;
    const float cmp = (D > 0.0f) ? p / (denom + 1e-10f) : 0.0f;
    g_row[row] = -logp;
    g_row[BROWS + row] = cmp;
}

__global__ void final_k(float* __restrict__ out)
{
    const int tid = threadIdx.x;  // 256
    float s = 0.f;
    for (int i = tid; i < 2 * BROWS; i += 256) s += g_row[i];
    #pragma unroll
    for (int o = 16; o > 0; o >>= 1) s += __shfl_xor_sync(0xffffffffu, s, o);
    __shared__ float red[8];
    if ((tid & 31) == 0) red[tid >> 5] = s;
    __syncthreads();
    if (tid == 0) {
        float t = 0.f;
        #pragma unroll
        for (int i = 0; i < 8; i++) t += red[i];
        out[0] = t / (float)BROWS;
    }
}

// ---------------------------------------------------------------------------
extern "C" void kernel_launch(void* const* d_in, const int* in_sizes, int n_in,
                              void* d_out, int out_size)
{
    const float* images = (const float*)d_in[0];
    const float* texts  = (const float*)d_in[1];
    const int*   labels = (const int*)d_in[2];
    const float* W_img  = (const float*)d_in[3];
    const float* W_txt  = (const float*)d_in[4];
    const float* lscale = (const float*)d_in[5];
    float* out = (float*)d_out;

    // Idempotent; needed for >48KB dynamic smem.
    cudaFuncSetAttribute(embed_norm_k, cudaFuncAttributeMaxDynamicSharedMemorySize, EN_SMEM);
    cudaFuncSetAttribute(logits_mma,   cudaFuncAttributeMaxDynamicSharedMemorySize, LG_SMEM);

    cvt2_k<<<dim3(BROWS * DDIM / 4 / 256, 2), 256>>>(images, texts);
    transpose2_k<<<dim3(EDIM / 32, DDIM / 32, 2), dim3(32, 32)>>>(W_img, W_txt);

    embed_norm_k<<<dim3(BROWS / 64, 2), 256, EN_SMEM>>>();

    sy_k<<<BROWS, 128>>>(labels);

    logits_mma<<<dim3(NT, NT), 256, LG_SMEM>>>(labels, lscale);

    rowloss_k<<<32, 128>>>(lscale);
    final_k<<<1, 256>>>(out);
}

// round 6
// speedup vs baseline: 5.6417x; 1.0207x over previous
#include <cuda_runtime.h>
#include <cuda_bf16.h>
#include <math.h>
#include <stdint.h>

// Problem constants
#define BROWS 4096
#define EDIM  512
#define DDIM  768
#define NT    32          // 4096 / 128 j-tiles

// ---------------- device scratch (allocation-free) ----------------
__device__ __nv_bfloat16 g_ah [BROWS * DDIM];   // images bf16
__device__ __nv_bfloat16 g_bh [BROWS * DDIM];   // texts  bf16
__device__ __nv_bfloat16 g_wti[EDIM * DDIM];    // W_img^T bf16 [512,768] K-contig
__device__ __nv_bfloat16 g_wtt[EDIM * DDIM];    // W_txt^T bf16
__device__ __nv_bfloat16 g_imgh[BROWS * EDIM];  // normalized bf16
__device__ __nv_bfloat16 g_txth[BROWS * EDIM];
__device__ float g_sy[BROWS];
__device__ float g_partS[NT * BROWS];
__device__ float g_partD[NT * BROWS];
__device__ float g_row[2 * BROWS];

// ---------------- PTX helpers (plain sm_80-era PTX) ----------------
__device__ __forceinline__ uint32_t s2u(const void* p) {
    uint32_t a;
    asm("{ .reg .u64 t; cvta.to.shared.u64 t, %1; cvt.u32.u64 %0, t; }"
        : "=r"(a) : "l"(p));
    return a;
}
__device__ __forceinline__ void cp16(uint32_t s, const void* g) {
    asm volatile("cp.async.cg.shared.global [%0], [%1], 16;" :: "r"(s), "l"(g));
}
__device__ __forceinline__ void cp_commit() { asm volatile("cp.async.commit_group;"); }
__device__ __forceinline__ void cp_wait0()  { asm volatile("cp.async.wait_group 0;"); }
__device__ __forceinline__ void cp_wait1()  { asm volatile("cp.async.wait_group 1;"); }

__device__ __forceinline__ void ldsm4(uint32_t* r, uint32_t addr) {
    asm volatile("ldmatrix.sync.aligned.m8n8.x4.shared.b16 {%0,%1,%2,%3}, [%4];"
                 : "=r"(r[0]), "=r"(r[1]), "=r"(r[2]), "=r"(r[3]) : "r"(addr));
}
__device__ __forceinline__ void mma16816(float* c, const uint32_t* a,
                                         uint32_t b0, uint32_t b1) {
    asm volatile(
        "mma.sync.aligned.m16n8k16.row.col.f32.bf16.bf16.f32 "
        "{%0,%1,%2,%3}, {%4,%5,%6,%7}, {%8,%9}, {%0,%1,%2,%3};"
        : "+f"(c[0]), "+f"(c[1]), "+f"(c[2]), "+f"(c[3])
        : "r"(a[0]), "r"(a[1]), "r"(a[2]), "r"(a[3]), "r"(b0), "r"(b1));
}

// Load ROWS x 64 bf16 (128B rows, SW128 xor swizzle) via cp.async; 256 threads.
template<int ROWS, int KEL>
__device__ __forceinline__ void load_rows(uint32_t sdst,
    const __nv_bfloat16* __restrict__ G, int k0)
{
    const int tid = threadIdx.x;
    #pragma unroll
    for (int i = 0; i < ROWS * 8 / 256; i++) {
        int idx = i * 256 + tid;
        int row = idx >> 3, ch = idx & 7;
        uint32_t soff = (uint32_t)row * 128u + ((uint32_t)(ch ^ (row & 7)) << 4);
        cp16(sdst + soff, G + (size_t)row * KEL + k0 + ch * 8);
    }
}

// ---------------------------------------------------------------------------
// fp32 -> bf16 conversion, both inputs in one launch (y = which)
// ---------------------------------------------------------------------------
__global__ void cvt2_k(const float* __restrict__ img, const float* __restrict__ txt)
{
    const int which = blockIdx.y;
    const float* src = which ? txt : img;
    __nv_bfloat16* dst = which ? g_bh : g_ah;
    int i = blockIdx.x * blockDim.x + threadIdx.x;    // grid.x*256 == n4
    float4 v = ((const float4*)src)[i];
    ((__nv_bfloat162*)dst)[2 * i]     = __floats2bfloat162_rn(v.x, v.y);
    ((__nv_bfloat162*)dst)[2 * i + 1] = __floats2bfloat162_rn(v.z, v.w);
}

// W [K=768, N=512] fp32 -> W^T [512, 768] bf16, both weights in one launch (z)
__global__ void transpose2_k(const float* __restrict__ Wi, const float* __restrict__ Wt2)
{
    const int which = blockIdx.z;
    const float* W = which ? Wt2 : Wi;
    __nv_bfloat16* Wt = which ? g_wtt : g_wti;
    __shared__ float t[32][33];
    const int n0 = blockIdx.x * 32, k0 = blockIdx.y * 32;
    const int tx = threadIdx.x, ty = threadIdx.y;
    t[ty][tx] = W[(size_t)(k0 + ty) * EDIM + n0 + tx];
    __syncthreads();
    Wt[(size_t)(n0 + ty) * DDIM + k0 + tx] = __float2bfloat16_rn(t[tx][ty]);
}

// ---------------------------------------------------------------------------
// Fused embed GEMM + row L2-normalize.
// C[64,512] = A_bf16[64,768] @ Wt_bf16[512,768]^T, then row-normalize -> bf16.
// 8 warps, each owns all 64 rows x 64 cols. 3-stage cp.async pipeline,
// ONE barrier per stage (ring distance 3 makes the bottom barrier redundant).
// ---------------------------------------------------------------------------
#define EN_STAGE 73728
#define EN_SMEM  (3 * EN_STAGE)   // 221184

__global__ __launch_bounds__(256, 1) void embed_norm_k()
{
    extern __shared__ char smem[];
    const uint32_t sb = s2u(smem);
    const int which = blockIdx.y;
    const __nv_bfloat16* A  = (which ? g_bh  : g_ah) + (size_t)blockIdx.x * 64 * DDIM;
    const __nv_bfloat16* Wt = which ? g_wtt : g_wti;
    __nv_bfloat16* out = which ? g_txth : g_imgh;
    const int m0 = blockIdx.x * 64;

    const int tid = threadIdx.x, lane = tid & 31, w = tid >> 5;
    const int l15 = lane & 15, lhi = lane >> 4;
    const int g = lane >> 2, tig = lane & 3;

    float c[4][8][4] = {};

    constexpr int ITERS = DDIM / 64;   // 12
    #pragma unroll
    for (int p = 0; p < 2; p++) {
        load_rows<64,  DDIM>(sb + p * EN_STAGE,        A,  p * 64);
        load_rows<512, DDIM>(sb + p * EN_STAGE + 8192, Wt, p * 64);
        cp_commit();
    }
    for (int s = 0; s < ITERS; s++) {
        if (s == ITERS - 1) cp_wait0(); else cp_wait1();
        __syncthreads();
        if (s + 2 < ITERS) {
            const int d = (s + 2) % 3;
            load_rows<64,  DDIM>(sb + d * EN_STAGE,        A,  (s + 2) * 64);
            load_rows<512, DDIM>(sb + d * EN_STAGE + 8192, Wt, (s + 2) * 64);
            cp_commit();
        }
        const uint32_t abase = sb + (s % 3) * EN_STAGE;
        const uint32_t bbase = abase + 8192;
        #pragma unroll
        for (int kk = 0; kk < 4; kk++) {
            const int ch = kk * 2 + lhi;
            uint32_t a[4][4];
            #pragma unroll
            for (int mt = 0; mt < 4; mt++) {
                int r = l15 + mt * 16;
                ldsm4(a[mt], abase + (uint32_t)r * 128u + ((uint32_t)(ch ^ (r & 7)) << 4));
            }
            uint32_t b[4][4];
            #pragma unroll
            for (int h = 0; h < 4; h++) {
                int r = w * 64 + h * 16 + l15;
                ldsm4(b[h], bbase + (uint32_t)r * 128u + ((uint32_t)(ch ^ (r & 7)) << 4));
            }
            #pragma unroll
            for (int mt = 0; mt < 4; mt++)
                #pragma unroll
                for (int nt = 0; nt < 8; nt++)
                    mma16816(c[mt][nt], a[mt], b[nt >> 1][nt & 1], b[nt >> 1][2 + (nt & 1)]);
        }
    }
    __syncthreads();   // all compute done before smem reuse below

    // ---- epilogue: row norms (reuse stage-0 smem) ----
    float* nsm = (float*)smem;   // [64][8] partials, then rnorm at [512..575]
    #pragma unroll
    for (int mt = 0; mt < 4; mt++) {
        float plo = 0.f, phi = 0.f;
        #pragma unroll
        for (int nt = 0; nt < 8; nt++) {
            plo += c[mt][nt][0] * c[mt][nt][0] + c[mt][nt][1] * c[mt][nt][1];
            phi += c[mt][nt][2] * c[mt][nt][2] + c[mt][nt][3] * c[mt][nt][3];
        }
        #pragma unroll
        for (int o = 1; o < 4; o <<= 1) {
            plo += __shfl_xor_sync(0xffffffffu, plo, o);
            phi += __shfl_xor_sync(0xffffffffu, phi, o);
        }
        if (tig == 0) {
            nsm[(mt * 16 + g) * 8 + w] = plo;
            nsm[(mt * 16 + g + 8) * 8 + w] = phi;
        }
    }
    __syncthreads();
    if (tid < 64) {
        float s = 0.f;
        #pragma unroll
        for (int i = 0; i < 8; i++) s += nsm[tid * 8 + i];
        nsm[512 + tid] = 1.0f / sqrtf(s);
    }
    __syncthreads();
    #pragma unroll
    for (int mt = 0; mt < 4; mt++) {
        const int rl = mt * 16 + g;
        const float rlo = nsm[512 + rl], rhi = nsm[512 + rl + 8];
        #pragma unroll
        for (int nt = 0; nt < 8; nt++) {
            const int col = w * 64 + nt * 8 + tig * 2;
            *(__nv_bfloat162*)(out + (size_t)(m0 + rl) * EDIM + col) =
                __floats2bfloat162_rn(c[mt][nt][0] * rlo, c[mt][nt][1] * rlo);
            *(__nv_bfloat162*)(out + (size_t)(m0 + rl + 8) * EDIM + col) =
                __floats2bfloat162_rn(c[mt][nt][2] * rhi, c[mt][nt][3] * rhi);
        }
    }
}

// ---------------------------------------------------------------------------
// s_y[i] = dot(imgh_i, txth_{labels[i]}) in fp32 — warp per row.
// 256 threads = 8 warps = 8 rows per block; 512 blocks.
// ---------------------------------------------------------------------------
__global__ void sy_k(const int* __restrict__ labels)
{
    const int lane = threadIdx.x & 31;
    const int row = blockIdx.x * 8 + (threadIdx.x >> 5);
    const int y = __ldg(labels + row);
    const uint4* a = (const uint4*)(g_imgh + (size_t)row * EDIM);
    const uint4* b = (const uint4*)(g_txth + (size_t)y * EDIM);
    float s = 0.f;
    #pragma unroll
    for (int it = 0; it < 2; it++) {
        uint4 av = a[it * 32 + lane];
        uint4 bv = b[it * 32 + lane];
        const uint32_t* ap = (const uint32_t*)&av;
        const uint32_t* bp = (const uint32_t*)&bv;
        #pragma unroll
        for (int q = 0; q < 4; q++) {
            float2 af = __bfloat1622float2(*(const __nv_bfloat162*)&ap[q]);
            float2 bf = __bfloat1622float2(*(const __nv_bfloat162*)&bp[q]);
            s += af.x * bf.x + af.y * bf.y;
        }
    }
    #pragma unroll
    for (int o = 16; o > 0; o >>= 1) s += __shfl_xor_sync(0xffffffffu, s, o);
    if (lane == 0) g_sy[row] = s;
}

// ---------------------------------------------------------------------------
// Logits GEMM (imgh @ txth^T) + fused softmax-partials epilogue.
// 128x128 tile, 3-stage cp.async pipeline, ONE barrier per stage.
// __launch_bounds__(256,2): cap regs at 128 so 2 CTAs/SM co-reside.
// ---------------------------------------------------------------------------
#define LG_SMEM 102912

__global__ __launch_bounds__(256, 2) void logits_mma(const int* __restrict__ labels,
                                                     const float* __restrict__ lsp)
{
    extern __shared__ char smem[];
    const uint32_t sb = s2u(smem);
    int*   slab = (int*)(smem + 98304);
    float* pS   = (float*)(smem + 98816);
    float* pD   = (float*)(smem + 100864);
    const int m0 = blockIdx.y * 128, n0 = blockIdx.x * 128;
    const int tid = threadIdx.x;
    if (tid < 128) slab[tid] = labels[n0 + tid];

    const __nv_bfloat16* A = g_imgh + (size_t)m0 * EDIM;
    const __nv_bfloat16* B = g_txth + (size_t)n0 * EDIM;
    const int lane = tid & 31, warp = tid >> 5;
    const int l15 = lane & 15, lhi = lane >> 4;
    const int warp_m = warp >> 2, warp_n = warp & 3;

    float c[4][4][4] = {};

    constexpr int ITERS = EDIM / 64;   // 8
    #pragma unroll
    for (int p = 0; p < 2; p++) {
        load_rows<128, EDIM>(sb + p * 32768u,          A, p * 64);
        load_rows<128, EDIM>(sb + p * 32768u + 16384u, B, p * 64);
        cp_commit();
    }
    for (int s = 0; s < ITERS; s++) {
        if (s == ITERS - 1) cp_wait0(); else cp_wait1();
        __syncthreads();
        if (s + 2 < ITERS) {
            const int d = (s + 2) % 3;
            load_rows<128, EDIM>(sb + d * 32768u,          A, (s + 2) * 64);
            load_rows<128, EDIM>(sb + d * 32768u + 16384u, B, (s + 2) * 64);
            cp_commit();
        }
        const uint32_t abase = sb + (uint32_t)(s % 3) * 32768u;
        const uint32_t bbase = abase + 16384u;
        const int arow = warp_m * 64 + l15;
        const int brow = warp_n * 32 + l15;
        #pragma unroll
        for (int kk = 0; kk < 4; kk++) {
            const int ch = kk * 2 + lhi;
            uint32_t a[4][4];
            #pragma unroll
            for (int mt = 0; mt < 4; mt++) {
                int r = arow + mt * 16;
                ldsm4(a[mt], abase + (uint32_t)r * 128u + ((uint32_t)(ch ^ (r & 7)) << 4));
            }
            uint32_t b[2][4];
            #pragma unroll
            for (int h = 0; h < 2; h++) {
                int r = brow + h * 16;
                ldsm4(b[h], bbase + (uint32_t)r * 128u + ((uint32_t)(ch ^ (r & 7)) << 4));
            }
            #pragma unroll
            for (int mt = 0; mt < 4; mt++)
                #pragma unroll
                for (int nt = 0; nt < 4; nt++)
                    mma16816(c[mt][nt], a[mt], b[nt >> 1][nt & 1], b[nt >> 1][2 + (nt & 1)]);
        }
    }
    __syncthreads();   // compute done before smem (pS/pD writes happen below)

    // ---- epilogue: exp + masked row-sum partials ----
    const int g = lane >> 2, tig = lane & 3;
    const float scale = expf(__ldg(lsp));

    #pragma unroll
    for (int mt = 0; mt < 4; mt++) {
        const int rl = warp_m * 64 + mt * 16 + g;
        const int rlo = m0 + rl, rhi = rlo + 8;
        const int lab_lo = __ldg(labels + rlo), lab_hi = __ldg(labels + rhi);
        const float sy_lo = __ldg(g_sy + rlo), sy_hi = __ldg(g_sy + rhi);
        float Slo = 0.f, Dlo = 0.f, Shi = 0.f, Dhi = 0.f;
        #pragma unroll
        for (int nt = 0; nt < 4; nt++) {
            const int jl = warp_n * 32 + nt * 8 + tig * 2;
            const int lab0 = slab[jl], lab1 = slab[jl + 1];
            const int j0 = n0 + jl, j1 = j0 + 1;
            float v, e;
            v = c[mt][nt][0]; e = __expf(scale * (v - 1.0f)); Slo += e;
            if (lab0 != lab_lo && j0 != lab_lo && v > sy_lo) Dlo += e;
            v = c[mt][nt][1]; e = __expf(scale * (v - 1.0f)); Slo += e;
            if (lab1 != lab_lo && j1 != lab_lo && v > sy_lo) Dlo += e;
            v = c[mt][nt][2]; e = __expf(scale * (v - 1.0f)); Shi += e;
            if (lab0 != lab_hi && j0 != lab_hi && v > sy_hi) Dhi += e;
            v = c[mt][nt][3]; e = __expf(scale * (v - 1.0f)); Shi += e;
            if (lab1 != lab_hi && j1 != lab_hi && v > sy_hi) Dhi += e;
        }
        #pragma unroll
        for (int o = 1; o < 4; o <<= 1) {
            Slo += __shfl_xor_sync(0xffffffffu, Slo, o);
            Dlo += __shfl_xor_sync(0xffffffffu, Dlo, o);
            Shi += __shfl_xor_sync(0xffffffffu, Shi, o);
            Dhi += __shfl_xor_sync(0xffffffffu, Dhi, o);
        }
        if (tig == 0) {
            pS[rl * 4 + warp_n] = Slo;  pD[rl * 4 + warp_n] = Dlo;
            pS[(rl + 8) * 4 + warp_n] = Shi;  pD[(rl + 8) * 4 + warp_n] = Dhi;
        }
    }
    __syncthreads();
    if (tid < 128) {
        float S = pS[tid * 4] + pS[tid * 4 + 1] + pS[tid * 4 + 2] + pS[tid * 4 + 3];
        float D = pD[tid * 4] + pD[tid * 4 + 1] + pD[tid * 4 + 2] + pD[tid * 4 + 3];
        g_partS[(size_t)blockIdx.x * BROWS + m0 + tid] = S;
        g_partD[(size_t)blockIdx.x * BROWS + m0 + tid] = D;
    }
}

// ---------------------------------------------------------------------------
// Per-row loss terms (deterministic fixed-order sum over 32 jtile partials)
// ---------------------------------------------------------------------------
__global__ void rowloss_k(const float* __restrict__ lsp)
{
    const int row = blockIdx.x * blockDim.x + threadIdx.x;
    const float scale = expf(*lsp);
    float S = 0.f, D = 0.f;
    #pragma unroll
    for (int t = 0; t < NT; t++) {
        S += g_partS[t * BROWS + row];
        D += g_partD[t * BROWS + row];
    }
    const float sy = g_sy[row] * scale;
    const float logp = (sy - scale) - logf(S);
    const float p = expf(logp);
    const float denom = D / S;
    const float cmp = (D > 0.0f) ? p / (denom + 1e-10f) : 0.0f;
    g_row[row] = -logp;
    g_row[BROWS + row] = cmp;
}

__global__ void final_k(float* __restrict__ out)
{
    const int tid = threadIdx.x;  // 256
    float s = 0.f;
    for (int i = tid; i < 2 * BROWS; i += 256) s += g_row[i];
    #pragma unroll
    for (int o = 16; o > 0; o >>= 1) s += __shfl_xor_sync(0xffffffffu, s, o);
    __shared__ float red[8];
    if ((tid & 31) == 0) red[tid >> 5] = s;
    __syncthreads();
    if (tid == 0) {
        float t = 0.f;
        #pragma unroll
        for (int i = 0; i < 8; i++) t += red[i];
        out[0] = t / (float)BROWS;
    }
}

// ---------------------------------------------------------------------------
extern "C" void kernel_launch(void* const* d_in, const int* in_sizes, int n_in,
                              void* d_out, int out_size)
{
    const float* images = (const float*)d_in[0];
    const float* texts  = (const float*)d_in[1];
    const int*   labels = (const int*)d_in[2];
    const float* W_img  = (const float*)d_in[3];
    const float* W_txt  = (const float*)d_in[4];
    const float* lscale = (const float*)d_in[5];
    float* out = (float*)d_out;

    // Idempotent; needed for >48KB dynamic smem.
    cudaFuncSetAttribute(embed_norm_k, cudaFuncAttributeMaxDynamicSharedMemorySize, EN_SMEM);
    cudaFuncSetAttribute(logits_mma,   cudaFuncAttributeMaxDynamicSharedMemorySize, LG_SMEM);

    cvt2_k<<<dim3(BROWS * DDIM / 4 / 256, 2), 256>>>(images, texts);
    transpose2_k<<<dim3(EDIM / 32, DDIM / 32, 2), dim3(32, 32)>>>(W_img, W_txt);

    embed_norm_k<<<dim3(BROWS / 64, 2), 256, EN_SMEM>>>();

    sy_k<<<BROWS / 8, 256>>>(labels);

    logits_mma<<<dim3(NT, NT), 256, LG_SMEM>>>(labels, lscale);

    rowloss_k<<<32, 128>>>(lscale);
    final_k<<<1, 256>>>(out);
}